// round 10
// baseline (speedup 1.0000x reference)
#include <cuda_runtime.h>
#include <cuda_bf16.h>
#include <cstdint>

// R10: algorithmic restructure. h[e] = f[row]@W1_top + f[col]@W1_bot, so:
//   Stage A (per NODE, 10x fewer FLOPs): uv[n] = f[n] @ [W1_top | W1_bot]
//            (100K x 128 x 256 bf16 tensor-core GEMM; b1 folded into u half)
//   Stage B (per EDGE, elementwise): h = u[row]+v[col]; PReLU; 128->2 dot;
//            log-softmax; NLL. Warp per edge, no MMA/barriers in the loop.

namespace {
constexpr int NHID     = 128;
constexpr int PRE_N    = 256;                 // u(128) | v(128)
constexpr int PRE_K    = 128;
constexpr int TILE_M   = 128;
constexpr int PRE_THREADS = 512;
constexpr int N_NODES_PAD = 100096;           // 782 * 128
constexpr int PRE_B_BYTES = PRE_K * PRE_N * 2;    // 64 KB
constexpr int PRE_A_BYTES = TILE_M * PRE_K * 2;   // 32 KB
constexpr int PRE_DSMEM   = PRE_B_BYTES + 2 * PRE_A_BYTES + 256;
constexpr int EDGE_THREADS = 256;
}

__device__ __align__(16) __nv_bfloat16 g_feat_bf16[(size_t)100000 * NHID];
__device__ __align__(16) __nv_bfloat16 g_w1pre[PRE_K * PRE_N];   // swizzled B image
__device__ __align__(16) __nv_bfloat16 g_uv[(size_t)N_NODES_PAD * PRE_N];
__device__ double g_loss_sum;

__device__ __forceinline__ uint32_t smem_u32(const void* p) {
    uint32_t a;
    asm("{ .reg .u64 t; cvta.to.shared.u64 t, %1; cvt.u32.u64 %0, t; }" : "=r"(a) : "l"(p));
    return a;
}

#define LDSM_X4(r, addr) \
    asm volatile("ldmatrix.sync.aligned.m8n8.x4.shared.b16 {%0,%1,%2,%3}, [%4];" \
        : "=r"((r)[0]), "=r"((r)[1]), "=r"((r)[2]), "=r"((r)[3]) : "r"(addr))
#define LDSM_X4T(r, addr) \
    asm volatile("ldmatrix.sync.aligned.m8n8.x4.trans.shared.b16 {%0,%1,%2,%3}, [%4];" \
        : "=r"((r)[0]), "=r"((r)[1]), "=r"((r)[2]), "=r"((r)[3]) : "r"(addr))

// ---------------- prep kernels ----------------
__global__ void hx_init_kernel() { g_loss_sum = 0.0; }

__global__ void hx_prep_feat(const float* __restrict__ f, int n4) {
    int i = blockIdx.x * blockDim.x + threadIdx.x;
    if (i < n4) {
        float4 v = reinterpret_cast<const float4*>(f)[i];
        __nv_bfloat162* dst = reinterpret_cast<__nv_bfloat162*>(g_feat_bf16);
        dst[i * 2]     = __floats2bfloat162_rn(v.x, v.y);
        dst[i * 2 + 1] = __floats2bfloat162_rn(v.z, v.w);
    }
}

// W1 [256,128] row-major -> B image [k=128 rows of 512B]: Bpre[k][n'] =
// W1[k + 128*(n'>=128)][n'&127]; chunk c=n'>>3 at cs=(c&24)|((c&7)^(k&7)).
__global__ void hx_prep_w1pre(const float* __restrict__ W1) {
    int idx = blockIdx.x * blockDim.x + threadIdx.x;   // 32768
    int k = idx >> 8, np = idx & 255;
    int srow = k + ((np >> 7) << 7);
    int scol = np & 127;
    int c  = np >> 3;
    int cs = (c & 24) | ((c & 7) ^ (k & 7));
    uint32_t off = (uint32_t)k * 512u + (uint32_t)cs * 16u + (uint32_t)(np & 7) * 2u;
    *reinterpret_cast<__nv_bfloat16*>(reinterpret_cast<char*>(g_w1pre) + off) =
        __float2bfloat16(W1[srow * 128 + scol]);
}

__global__ void hx_final_kernel(float* out, int E) {
    out[0] = (float)(-g_loss_sum / (double)E);
}

// ---------------- Stage A: node GEMM uv = feat @ [W1_top | W1_bot] ----------------
__device__ __forceinline__ void pre_gather(uint32_t Abuf, int t, int tid) {
    // thread -> row r = tid>>2, chunks (tid&3)*4 .. +3 (16B each) of 256B row
    const int r = tid >> 2, part = tid & 3;
    int node = t * TILE_M + r;
    if (node > 99999) node = 99999;
    const char* src = reinterpret_cast<const char*>(g_feat_bf16) + (size_t)node * 256;
    #pragma unroll
    for (int q = 0; q < 4; ++q) {
        const int c  = part * 4 + q;
        const int cs = (c & 8) | ((c & 7) ^ (r & 7));
        asm volatile("cp.async.cg.shared.global [%0], [%1], 16;"
                     :: "r"(Abuf + (uint32_t)r * 256u + (uint32_t)cs * 16u),
                        "l"(src + c * 16) : "memory");
    }
}

__global__ __launch_bounds__(PRE_THREADS, 1)
void hx_pre_gemm(const float* __restrict__ b1, int ntiles)
{
    extern __shared__ char dyn[];
    const int tid  = threadIdx.x;
    const int lane = tid & 31;
    const int warp = tid >> 5;

    const uint32_t dynb = smem_u32(dyn);
    const uint32_t base = (dynb + 255u) & ~255u;
    const uint32_t Bsm  = base;
    const uint32_t Asm0 = base + PRE_B_BYTES;

    // warp tile m64 x n32: grid 2m x 8n over 128 x 256
    const int warp_m = warp & 1, warp_n = warp >> 1;
    const int m_base = warp_m * 64, n_base = warp_n * 32;
    const int quad = lane >> 2, qlane = lane & 3;

    // prologue: A(t0) + stage B
    if (blockIdx.x < ntiles) pre_gather(Asm0, blockIdx.x, tid);
    asm volatile("cp.async.commit_group;" ::: "memory");
    {
        char* dst = dyn + (base - dynb);
        const int4* s = reinterpret_cast<const int4*>(g_w1pre);
        int4* d = reinterpret_cast<int4*>(dst);
        for (int i = tid; i < PRE_B_BYTES / 16; i += PRE_THREADS) d[i] = s[i];
    }

    // per-thread bias (folded into u half only)
    float2 bb[4];
    #pragma unroll
    for (int j = 0; j < 4; ++j) {
        const int n = n_base + j * 8 + qlane * 2;
        bb[j] = (n < 128) ? make_float2(b1[n], b1[n + 1]) : make_float2(0.f, 0.f);
    }

    uint32_t rowA[4];
    #pragma unroll
    for (int i = 0; i < 4; ++i)
        rowA[i] = (uint32_t)(m_base + i * 16 + (lane & 15)) * 256u;
    const int xA  = lane & 7;
    const int csA = lane >> 4;

    uint32_t bBase[2];
    {
        const int kr = lane & 15;
        #pragma unroll
        for (int j2 = 0; j2 < 2; ++j2) {
            const int cn = warp_n * 4 + j2 * 2 + (lane >> 4);
            const int cs = (cn & 24) | ((cn & 7) ^ (kr & 7));
            bBase[j2] = Bsm + (uint32_t)kr * 512u + (uint32_t)cs * 16u;
        }
    }

    int li = 0;
    for (int t = blockIdx.x; t < ntiles; t += gridDim.x, ++li) {
        const int buf = li & 1;
        const uint32_t Abuf = Asm0 + (uint32_t)buf * PRE_A_BYTES;

        asm volatile("cp.async.wait_group 0;" ::: "memory");
        __syncthreads();

        const int tn = t + gridDim.x;
        if (tn < ntiles) {
            pre_gather(Asm0 + (uint32_t)(buf ^ 1) * PRE_A_BYTES, tn, tid);
            asm volatile("cp.async.commit_group;" ::: "memory");
        }

        float acc[4][4][4];
        #pragma unroll
        for (int i = 0; i < 4; ++i)
            #pragma unroll
            for (int j = 0; j < 4; ++j) {
                acc[i][j][0] = 0.f; acc[i][j][1] = 0.f;
                acc[i][j][2] = 0.f; acc[i][j][3] = 0.f;
            }

        #pragma unroll
        for (int ks = 0; ks < 8; ++ks) {
            uint32_t b[2][4], a[4][4];
            #pragma unroll
            for (int j2 = 0; j2 < 2; ++j2)
                LDSM_X4T(b[j2], bBase[j2] + (uint32_t)ks * 8192u);
            const int c  = 2 * ks + csA;
            const int cs = (c & 8) | ((c & 7) ^ xA);
            #pragma unroll
            for (int i = 0; i < 4; ++i)
                LDSM_X4(a[i], Abuf + rowA[i] + (uint32_t)cs * 16u);
            #pragma unroll
            for (int i = 0; i < 4; ++i)
                #pragma unroll
                for (int j = 0; j < 4; ++j) {
                    const uint32_t bb0 = b[j >> 1][(j & 1) * 2];
                    const uint32_t bb1 = b[j >> 1][(j & 1) * 2 + 1];
                    asm volatile(
                        "mma.sync.aligned.m16n8k16.row.col.f32.bf16.bf16.f32 "
                        "{%0,%1,%2,%3}, {%4,%5,%6,%7}, {%8,%9}, {%0,%1,%2,%3};"
                        : "+f"(acc[i][j][0]), "+f"(acc[i][j][1]),
                          "+f"(acc[i][j][2]), "+f"(acc[i][j][3])
                        : "r"(a[i][0]), "r"(a[i][1]), "r"(a[i][2]), "r"(a[i][3]),
                          "r"(bb0), "r"(bb1));
                }
        }

        // store fragments (+bias on u half) as bf16
        #pragma unroll
        for (int i = 0; i < 4; ++i) {
            const int m0 = m_base + i * 16 + quad;
            const size_t r0 = (size_t)(t * TILE_M + m0) * PRE_N;
            const size_t r1 = (size_t)(t * TILE_M + m0 + 8) * PRE_N;
            #pragma unroll
            for (int j = 0; j < 4; ++j) {
                const int n = n_base + j * 8 + qlane * 2;
                __nv_bfloat162 p = __floats2bfloat162_rn(acc[i][j][0] + bb[j].x,
                                                         acc[i][j][1] + bb[j].y);
                __nv_bfloat162 q = __floats2bfloat162_rn(acc[i][j][2] + bb[j].x,
                                                         acc[i][j][3] + bb[j].y);
                *reinterpret_cast<__nv_bfloat162*>(&g_uv[r0 + n]) = p;
                *reinterpret_cast<__nv_bfloat162*>(&g_uv[r1 + n]) = q;
            }
        }
        __syncthreads();   // all warps done with Abuf before next overwrite
    }
}

// ---------------- Stage B: per-edge elementwise loss ----------------
__global__ __launch_bounds__(EDGE_THREADS, 1)
void hx_edge(const float* __restrict__ alpha,
             const float* __restrict__ W2,
             const float* __restrict__ b2,
             const int* __restrict__ row,
             const int* __restrict__ col,
             const int* __restrict__ label,
             int E)
{
    __shared__ double s_dsum;
    const int tid  = threadIdx.x;
    const int lane = tid & 31;
    const int warp = tid >> 5;
    if (tid == 0) s_dsum = 0.0;
    __syncthreads();

    const int c0 = lane * 4;
    const float4 av = *reinterpret_cast<const float4*>(&alpha[c0]);
    // W2 [128,2] row-major
    const float4 w2a = *reinterpret_cast<const float4*>(&W2[c0 * 2]);
    const float4 w2b = *reinterpret_cast<const float4*>(&W2[c0 * 2 + 4]);
    const float w20x = w2a.x, w21x = w2a.y, w20y = w2a.z, w21y = w2a.w;
    const float w20z = w2b.x, w21z = w2b.y, w20w = w2b.z, w21w = w2b.w;
    const float bias0 = b2[0], bias1 = b2[1];

    const int gw = blockIdx.x * (EDGE_THREADS / 32) + warp;
    const int stride = gridDim.x * (EDGE_THREADS / 32);
    double dsum = 0.0;

    for (int e = gw; e < E; e += stride) {
        const int r = __ldg(&row[e]);
        const int c = __ldg(&col[e]);
        const int y = (__ldg(&label[r]) == __ldg(&label[c])) ? 1 : 0;

        const uint2 ub = *reinterpret_cast<const uint2*>(&g_uv[(size_t)r * PRE_N + c0]);
        const uint2 vb = *reinterpret_cast<const uint2*>(&g_uv[(size_t)c * PRE_N + 128 + c0]);

        const float2 u0 = __bfloat1622float2(*reinterpret_cast<const __nv_bfloat162*>(&ub.x));
        const float2 u1 = __bfloat1622float2(*reinterpret_cast<const __nv_bfloat162*>(&ub.y));
        const float2 v0 = __bfloat1622float2(*reinterpret_cast<const __nv_bfloat162*>(&vb.x));
        const float2 v1 = __bfloat1622float2(*reinterpret_cast<const __nv_bfloat162*>(&vb.y));

        float p0 = 0.f, p1 = 0.f;
        {
            float h, ph;
            h = u0.x + v0.x; ph = fmaf(av.x, fminf(h, 0.f), fmaxf(h, 0.f));
            p0 = fmaf(ph, w20x, p0); p1 = fmaf(ph, w21x, p1);
            h = u0.y + v0.y; ph = fmaf(av.y, fminf(h, 0.f), fmaxf(h, 0.f));
            p0 = fmaf(ph, w20y, p0); p1 = fmaf(ph, w21y, p1);
            h = u1.x + v1.x; ph = fmaf(av.z, fminf(h, 0.f), fmaxf(h, 0.f));
            p0 = fmaf(ph, w20z, p0); p1 = fmaf(ph, w21z, p1);
            h = u1.y + v1.y; ph = fmaf(av.w, fminf(h, 0.f), fmaxf(h, 0.f));
            p0 = fmaf(ph, w20w, p0); p1 = fmaf(ph, w21w, p1);
        }
        #pragma unroll
        for (int off = 16; off > 0; off >>= 1) {
            p0 += __shfl_xor_sync(0xffffffffu, p0, off);
            p1 += __shfl_xor_sync(0xffffffffu, p1, off);
        }
        if (lane == 0) {
            const float l0 = p0 + bias0;
            const float l1 = p1 + bias1;
            const float mx  = fmaxf(l0, l1);
            const float lse = mx + log1pf(expf(-fabsf(l0 - l1)));
            dsum += (double)((y ? l1 : l0) - lse);
        }
    }

    if (lane == 0) atomicAdd(&s_dsum, dsum);
    __syncthreads();
    if (tid == 0) atomicAdd(&g_loss_sum, s_dsum);
}

extern "C" void kernel_launch(void* const* d_in, const int* in_sizes, int n_in,
                              void* d_out, int out_size) {
    const float* feature = (const float*)d_in[0];
    const float* W1      = (const float*)d_in[1];
    const float* b1      = (const float*)d_in[2];
    const float* alpha   = (const float*)d_in[3];
    const float* W2      = (const float*)d_in[4];
    const float* b2      = (const float*)d_in[5];
    const int*   row     = (const int*)d_in[6];
    const int*   col     = (const int*)d_in[7];
    const int*   label   = (const int*)d_in[8];
    const int E  = in_sizes[6];
    const int nf = in_sizes[0];
    float* out = (float*)d_out;

    int sms = 148;
    cudaDeviceGetAttribute(&sms, cudaDevAttrMultiProcessorCount, 0);
    cudaFuncSetAttribute(hx_pre_gemm,
                         cudaFuncAttributeMaxDynamicSharedMemorySize, PRE_DSMEM);

    hx_init_kernel<<<1, 1>>>();
    hx_prep_feat<<<(nf / 4 + 255) / 256, 256>>>(feature, nf / 4);
    hx_prep_w1pre<<<(PRE_K * PRE_N) / 256, 256>>>(W1);

    const int nnodes = in_sizes[0] / NHID;
    const int ntiles = (nnodes + TILE_M - 1) / TILE_M;
    hx_pre_gemm<<<sms, PRE_THREADS, PRE_DSMEM>>>(b1, ntiles);

    hx_edge<<<sms * 8, EDGE_THREADS>>>(alpha, W2, b2, row, col, label, E);
    hx_final_kernel<<<1, 1>>>(out, E);
}

// round 11
// speedup vs baseline: 1.1739x; 1.1739x over previous
#include <cuda_runtime.h>
#include <cuda_bf16.h>
#include <cstdint>

// R11: R10 decomposition (node GEMM + elementwise edge pass), with the edge
// kernel software-pipelined: compute(e) overlaps uv/label loads for e+1 and
// index loads for e+2 -> MLP ~8 per warp instead of a serial LDG chain.

namespace {
constexpr int NHID     = 128;
constexpr int PRE_N    = 256;                 // u(128) | v(128)
constexpr int PRE_K    = 128;
constexpr int TILE_M   = 128;
constexpr int PRE_THREADS = 512;
constexpr int N_NODES_PAD = 100096;           // 782 * 128
constexpr int PRE_B_BYTES = PRE_K * PRE_N * 2;    // 64 KB
constexpr int PRE_A_BYTES = TILE_M * PRE_K * 2;   // 32 KB
constexpr int PRE_DSMEM   = PRE_B_BYTES + 2 * PRE_A_BYTES + 256;
constexpr int EDGE_THREADS = 256;
}

__device__ __align__(16) __nv_bfloat16 g_feat_bf16[(size_t)100000 * NHID];
__device__ __align__(16) __nv_bfloat16 g_w1pre[PRE_K * PRE_N];   // swizzled B image
__device__ __align__(16) __nv_bfloat16 g_uv[(size_t)N_NODES_PAD * PRE_N];
__device__ double g_loss_sum;

__device__ __forceinline__ uint32_t smem_u32(const void* p) {
    uint32_t a;
    asm("{ .reg .u64 t; cvta.to.shared.u64 t, %1; cvt.u32.u64 %0, t; }" : "=r"(a) : "l"(p));
    return a;
}

#define LDSM_X4(r, addr) \
    asm volatile("ldmatrix.sync.aligned.m8n8.x4.shared.b16 {%0,%1,%2,%3}, [%4];" \
        : "=r"((r)[0]), "=r"((r)[1]), "=r"((r)[2]), "=r"((r)[3]) : "r"(addr))
#define LDSM_X4T(r, addr) \
    asm volatile("ldmatrix.sync.aligned.m8n8.x4.trans.shared.b16 {%0,%1,%2,%3}, [%4];" \
        : "=r"((r)[0]), "=r"((r)[1]), "=r"((r)[2]), "=r"((r)[3]) : "r"(addr))

// ---------------- prep kernels ----------------
__global__ void hx_init_kernel() { g_loss_sum = 0.0; }

__global__ void hx_prep_feat(const float* __restrict__ f, int n4) {
    int i = blockIdx.x * blockDim.x + threadIdx.x;
    if (i < n4) {
        float4 v = reinterpret_cast<const float4*>(f)[i];
        __nv_bfloat162* dst = reinterpret_cast<__nv_bfloat162*>(g_feat_bf16);
        dst[i * 2]     = __floats2bfloat162_rn(v.x, v.y);
        dst[i * 2 + 1] = __floats2bfloat162_rn(v.z, v.w);
    }
}

__global__ void hx_prep_w1pre(const float* __restrict__ W1) {
    int idx = blockIdx.x * blockDim.x + threadIdx.x;   // 32768
    int k = idx >> 8, np = idx & 255;
    int srow = k + ((np >> 7) << 7);
    int scol = np & 127;
    int c  = np >> 3;
    int cs = (c & 24) | ((c & 7) ^ (k & 7));
    uint32_t off = (uint32_t)k * 512u + (uint32_t)cs * 16u + (uint32_t)(np & 7) * 2u;
    *reinterpret_cast<__nv_bfloat16*>(reinterpret_cast<char*>(g_w1pre) + off) =
        __float2bfloat16(W1[srow * 128 + scol]);
}

__global__ void hx_final_kernel(float* out, int E) {
    out[0] = (float)(-g_loss_sum / (double)E);
}

// ---------------- Stage A: node GEMM uv = feat @ [W1_top | W1_bot] ----------------
__device__ __forceinline__ void pre_gather(uint32_t Abuf, int t, int tid) {
    const int r = tid >> 2, part = tid & 3;
    int node = t * TILE_M + r;
    if (node > 99999) node = 99999;
    const char* src = reinterpret_cast<const char*>(g_feat_bf16) + (size_t)node * 256;
    #pragma unroll
    for (int q = 0; q < 4; ++q) {
        const int c  = part * 4 + q;
        const int cs = (c & 8) | ((c & 7) ^ (r & 7));
        asm volatile("cp.async.cg.shared.global [%0], [%1], 16;"
                     :: "r"(Abuf + (uint32_t)r * 256u + (uint32_t)cs * 16u),
                        "l"(src + c * 16) : "memory");
    }
}

__global__ __launch_bounds__(PRE_THREADS, 1)
void hx_pre_gemm(const float* __restrict__ b1, int ntiles)
{
    extern __shared__ char dyn[];
    const int tid  = threadIdx.x;
    const int lane = tid & 31;
    const int warp = tid >> 5;

    const uint32_t dynb = smem_u32(dyn);
    const uint32_t base = (dynb + 255u) & ~255u;
    const uint32_t Bsm  = base;
    const uint32_t Asm0 = base + PRE_B_BYTES;

    const int warp_m = warp & 1, warp_n = warp >> 1;
    const int m_base = warp_m * 64, n_base = warp_n * 32;
    const int quad = lane >> 2, qlane = lane & 3;

    if (blockIdx.x < ntiles) pre_gather(Asm0, blockIdx.x, tid);
    asm volatile("cp.async.commit_group;" ::: "memory");
    {
        char* dst = dyn + (base - dynb);
        const int4* s = reinterpret_cast<const int4*>(g_w1pre);
        int4* d = reinterpret_cast<int4*>(dst);
        for (int i = tid; i < PRE_B_BYTES / 16; i += PRE_THREADS) d[i] = s[i];
    }

    float2 bb[4];
    #pragma unroll
    for (int j = 0; j < 4; ++j) {
        const int n = n_base + j * 8 + qlane * 2;
        bb[j] = (n < 128) ? make_float2(b1[n], b1[n + 1]) : make_float2(0.f, 0.f);
    }

    uint32_t rowA[4];
    #pragma unroll
    for (int i = 0; i < 4; ++i)
        rowA[i] = (uint32_t)(m_base + i * 16 + (lane & 15)) * 256u;
    const int xA  = lane & 7;
    const int csA = lane >> 4;

    uint32_t bBase[2];
    {
        const int kr = lane & 15;
        #pragma unroll
        for (int j2 = 0; j2 < 2; ++j2) {
            const int cn = warp_n * 4 + j2 * 2 + (lane >> 4);
            const int cs = (cn & 24) | ((cn & 7) ^ (kr & 7));
            bBase[j2] = Bsm + (uint32_t)kr * 512u + (uint32_t)cs * 16u;
        }
    }

    int li = 0;
    for (int t = blockIdx.x; t < ntiles; t += gridDim.x, ++li) {
        const int buf = li & 1;
        const uint32_t Abuf = Asm0 + (uint32_t)buf * PRE_A_BYTES;

        asm volatile("cp.async.wait_group 0;" ::: "memory");
        __syncthreads();

        const int tn = t + gridDim.x;
        if (tn < ntiles) {
            pre_gather(Asm0 + (uint32_t)(buf ^ 1) * PRE_A_BYTES, tn, tid);
            asm volatile("cp.async.commit_group;" ::: "memory");
        }

        float acc[4][4][4];
        #pragma unroll
        for (int i = 0; i < 4; ++i)
            #pragma unroll
            for (int j = 0; j < 4; ++j) {
                acc[i][j][0] = 0.f; acc[i][j][1] = 0.f;
                acc[i][j][2] = 0.f; acc[i][j][3] = 0.f;
            }

        #pragma unroll
        for (int ks = 0; ks < 8; ++ks) {
            uint32_t b[2][4], a[4][4];
            #pragma unroll
            for (int j2 = 0; j2 < 2; ++j2)
                LDSM_X4T(b[j2], bBase[j2] + (uint32_t)ks * 8192u);
            const int c  = 2 * ks + csA;
            const int cs = (c & 8) | ((c & 7) ^ xA);
            #pragma unroll
            for (int i = 0; i < 4; ++i)
                LDSM_X4(a[i], Abuf + rowA[i] + (uint32_t)cs * 16u);
            #pragma unroll
            for (int i = 0; i < 4; ++i)
                #pragma unroll
                for (int j = 0; j < 4; ++j) {
                    const uint32_t bb0 = b[j >> 1][(j & 1) * 2];
                    const uint32_t bb1 = b[j >> 1][(j & 1) * 2 + 1];
                    asm volatile(
                        "mma.sync.aligned.m16n8k16.row.col.f32.bf16.bf16.f32 "
                        "{%0,%1,%2,%3}, {%4,%5,%6,%7}, {%8,%9}, {%0,%1,%2,%3};"
                        : "+f"(acc[i][j][0]), "+f"(acc[i][j][1]),
                          "+f"(acc[i][j][2]), "+f"(acc[i][j][3])
                        : "r"(a[i][0]), "r"(a[i][1]), "r"(a[i][2]), "r"(a[i][3]),
                          "r"(bb0), "r"(bb1));
                }
        }

        #pragma unroll
        for (int i = 0; i < 4; ++i) {
            const int m0 = m_base + i * 16 + quad;
            const size_t r0 = (size_t)(t * TILE_M + m0) * PRE_N;
            const size_t r1 = (size_t)(t * TILE_M + m0 + 8) * PRE_N;
            #pragma unroll
            for (int j = 0; j < 4; ++j) {
                const int n = n_base + j * 8 + qlane * 2;
                __nv_bfloat162 p = __floats2bfloat162_rn(acc[i][j][0] + bb[j].x,
                                                         acc[i][j][1] + bb[j].y);
                __nv_bfloat162 q = __floats2bfloat162_rn(acc[i][j][2] + bb[j].x,
                                                         acc[i][j][3] + bb[j].y);
                *reinterpret_cast<__nv_bfloat162*>(&g_uv[r0 + n]) = p;
                *reinterpret_cast<__nv_bfloat162*>(&g_uv[r1 + n]) = q;
            }
        }
        __syncthreads();
    }
}

// ---------------- Stage B: per-edge elementwise loss (pipelined) ----------------
__global__ __launch_bounds__(EDGE_THREADS, 1)
void hx_edge(const float* __restrict__ alpha,
             const float* __restrict__ W2,
             const float* __restrict__ b2,
             const int* __restrict__ row,
             const int* __restrict__ col,
             const int* __restrict__ label,
             int E)
{
    __shared__ double s_dsum;
    const int tid  = threadIdx.x;
    const int lane = tid & 31;
    const int warp = tid >> 5;
    if (tid == 0) s_dsum = 0.0;
    __syncthreads();

    const int c0 = lane * 4;
    const float4 av  = *reinterpret_cast<const float4*>(&alpha[c0]);
    const float4 w2a = *reinterpret_cast<const float4*>(&W2[c0 * 2]);
    const float4 w2b = *reinterpret_cast<const float4*>(&W2[c0 * 2 + 4]);
    const float bias0 = b2[0], bias1 = b2[1];

    const int gw = blockIdx.x * (EDGE_THREADS / 32) + warp;
    const int stride = gridDim.x * (EDGE_THREADS / 32);
    double dsum = 0.0;

    if (gw < E) {
        // ---- pipeline prologue ----
        int e  = gw;
        int rc = __ldg(&row[e]), cc = __ldg(&col[e]);        // cur indices
        int la = __ldg(&label[rc]), lb = __ldg(&label[cc]);  // cur labels
        uint2 ub = *reinterpret_cast<const uint2*>(&g_uv[(size_t)rc * PRE_N + c0]);
        uint2 vb = *reinterpret_cast<const uint2*>(&g_uv[(size_t)cc * PRE_N + 128 + c0]);
        int rn = 0, cn = 0;
        if (e + stride < E) { rn = __ldg(&row[e + stride]); cn = __ldg(&col[e + stride]); }

        for (; e < E; e += stride) {
            // ---- issue loads for e+stride (uv, labels) and e+2*stride (indices) ----
            uint2 ubn, vbn; int lan = 0, lbn = 0;
            const bool has1 = (e + stride) < E;
            if (has1) {
                ubn = *reinterpret_cast<const uint2*>(&g_uv[(size_t)rn * PRE_N + c0]);
                vbn = *reinterpret_cast<const uint2*>(&g_uv[(size_t)cn * PRE_N + 128 + c0]);
                lan = __ldg(&label[rn]);
                lbn = __ldg(&label[cn]);
            } else { ubn = make_uint2(0u, 0u); vbn = make_uint2(0u, 0u); }
            int rn2 = 0, cn2 = 0;
            if (e + 2 * stride < E) {
                rn2 = __ldg(&row[e + 2 * stride]);
                cn2 = __ldg(&col[e + 2 * stride]);
            }

            // ---- compute current edge ----
            const float2 u0 = __bfloat1622float2(*reinterpret_cast<const __nv_bfloat162*>(&ub.x));
            const float2 u1 = __bfloat1622float2(*reinterpret_cast<const __nv_bfloat162*>(&ub.y));
            const float2 v0 = __bfloat1622float2(*reinterpret_cast<const __nv_bfloat162*>(&vb.x));
            const float2 v1 = __bfloat1622float2(*reinterpret_cast<const __nv_bfloat162*>(&vb.y));

            float p0 = 0.f, p1 = 0.f;
            {
                float h, ph;
                h = u0.x + v0.x; ph = fmaf(av.x, fminf(h, 0.f), fmaxf(h, 0.f));
                p0 = fmaf(ph, w2a.x, p0); p1 = fmaf(ph, w2a.y, p1);
                h = u0.y + v0.y; ph = fmaf(av.y, fminf(h, 0.f), fmaxf(h, 0.f));
                p0 = fmaf(ph, w2a.z, p0); p1 = fmaf(ph, w2a.w, p1);
                h = u1.x + v1.x; ph = fmaf(av.z, fminf(h, 0.f), fmaxf(h, 0.f));
                p0 = fmaf(ph, w2b.x, p0); p1 = fmaf(ph, w2b.y, p1);
                h = u1.y + v1.y; ph = fmaf(av.w, fminf(h, 0.f), fmaxf(h, 0.f));
                p0 = fmaf(ph, w2b.z, p0); p1 = fmaf(ph, w2b.w, p1);
            }
            #pragma unroll
            for (int off = 16; off > 0; off >>= 1) {
                p0 += __shfl_xor_sync(0xffffffffu, p0, off);
                p1 += __shfl_xor_sync(0xffffffffu, p1, off);
            }
            if (lane == 0) {
                const int y = (la == lb);
                const float l0 = p0 + bias0;
                const float l1 = p1 + bias1;
                const float mx  = fmaxf(l0, l1);
                const float lse = mx + log1pf(expf(-fabsf(l0 - l1)));
                dsum += (double)((y ? l1 : l0) - lse);
            }

            // ---- rotate pipeline ----
            ub = ubn; vb = vbn; la = lan; lb = lbn;
            rn = rn2; cn = cn2;
        }
    }

    if (lane == 0) atomicAdd(&s_dsum, dsum);
    __syncthreads();
    if (tid == 0) atomicAdd(&g_loss_sum, s_dsum);
}

extern "C" void kernel_launch(void* const* d_in, const int* in_sizes, int n_in,
                              void* d_out, int out_size) {
    const float* feature = (const float*)d_in[0];
    const float* W1      = (const float*)d_in[1];
    const float* b1      = (const float*)d_in[2];
    const float* alpha   = (const float*)d_in[3];
    const float* W2      = (const float*)d_in[4];
    const float* b2      = (const float*)d_in[5];
    const int*   row     = (const int*)d_in[6];
    const int*   col     = (const int*)d_in[7];
    const int*   label   = (const int*)d_in[8];
    const int E  = in_sizes[6];
    const int nf = in_sizes[0];
    float* out = (float*)d_out;

    int sms = 148;
    cudaDeviceGetAttribute(&sms, cudaDevAttrMultiProcessorCount, 0);
    cudaFuncSetAttribute(hx_pre_gemm,
                         cudaFuncAttributeMaxDynamicSharedMemorySize, PRE_DSMEM);

    hx_init_kernel<<<1, 1>>>();
    hx_prep_feat<<<(nf / 4 + 255) / 256, 256>>>(feature, nf / 4);
    hx_prep_w1pre<<<(PRE_K * PRE_N) / 256, 256>>>(W1);

    const int nnodes = in_sizes[0] / NHID;
    const int ntiles = (nnodes + TILE_M - 1) / TILE_M;
    hx_pre_gemm<<<sms, PRE_THREADS, PRE_DSMEM>>>(b1, ntiles);

    hx_edge<<<sms * 16, EDGE_THREADS>>>(alpha, W2, b2, row, col, label, E);
    hx_final_kernel<<<1, 1>>>(out, E);
}

// round 12
// speedup vs baseline: 1.6135x; 1.3745x over previous
#include <cuda_runtime.h>
#include <cuda_bf16.h>
#include <cstdint>

// R12: node-GEMM decomposition (Stage A unchanged from R11, 36us) + rewritten
// edge pass: 4 edges/warp, 8 lanes x 16 channels each -> 1.5 shfl/edge
// (vs 10), coalesced uint4 uv loads, index/label prefetch pipeline,
// persistent grid (2 CTAs/SM).

namespace {
constexpr int NHID     = 128;
constexpr int PRE_N    = 256;                 // u(128) | v(128)
constexpr int PRE_K    = 128;
constexpr int TILE_M   = 128;
constexpr int PRE_THREADS = 512;
constexpr int N_NODES_PAD = 100096;           // 782 * 128
constexpr int PRE_B_BYTES = PRE_K * PRE_N * 2;    // 64 KB
constexpr int PRE_A_BYTES = TILE_M * PRE_K * 2;   // 32 KB
constexpr int PRE_DSMEM   = PRE_B_BYTES + 2 * PRE_A_BYTES + 256;
constexpr int EDGE_THREADS = 256;
}

__device__ __align__(16) __nv_bfloat16 g_feat_bf16[(size_t)100000 * NHID];
__device__ __align__(16) __nv_bfloat16 g_w1pre[PRE_K * PRE_N];   // swizzled B image
__device__ __align__(16) __nv_bfloat16 g_uv[(size_t)N_NODES_PAD * PRE_N];
__device__ double g_loss_sum;

__device__ __forceinline__ uint32_t smem_u32(const void* p) {
    uint32_t a;
    asm("{ .reg .u64 t; cvta.to.shared.u64 t, %1; cvt.u32.u64 %0, t; }" : "=r"(a) : "l"(p));
    return a;
}

#define LDSM_X4(r, addr) \
    asm volatile("ldmatrix.sync.aligned.m8n8.x4.shared.b16 {%0,%1,%2,%3}, [%4];" \
        : "=r"((r)[0]), "=r"((r)[1]), "=r"((r)[2]), "=r"((r)[3]) : "r"(addr))
#define LDSM_X4T(r, addr) \
    asm volatile("ldmatrix.sync.aligned.m8n8.x4.trans.shared.b16 {%0,%1,%2,%3}, [%4];" \
        : "=r"((r)[0]), "=r"((r)[1]), "=r"((r)[2]), "=r"((r)[3]) : "r"(addr))

// ---------------- prep kernels ----------------
__global__ void hx_init_kernel() { g_loss_sum = 0.0; }

__global__ void hx_prep_feat(const float* __restrict__ f, int n4) {
    int i = blockIdx.x * blockDim.x + threadIdx.x;
    if (i < n4) {
        float4 v = reinterpret_cast<const float4*>(f)[i];
        __nv_bfloat162* dst = reinterpret_cast<__nv_bfloat162*>(g_feat_bf16);
        dst[i * 2]     = __floats2bfloat162_rn(v.x, v.y);
        dst[i * 2 + 1] = __floats2bfloat162_rn(v.z, v.w);
    }
}

__global__ void hx_prep_w1pre(const float* __restrict__ W1) {
    int idx = blockIdx.x * blockDim.x + threadIdx.x;   // 32768
    int k = idx >> 8, np = idx & 255;
    int srow = k + ((np >> 7) << 7);
    int scol = np & 127;
    int c  = np >> 3;
    int cs = (c & 24) | ((c & 7) ^ (k & 7));
    uint32_t off = (uint32_t)k * 512u + (uint32_t)cs * 16u + (uint32_t)(np & 7) * 2u;
    *reinterpret_cast<__nv_bfloat16*>(reinterpret_cast<char*>(g_w1pre) + off) =
        __float2bfloat16(W1[srow * 128 + scol]);
}

__global__ void hx_final_kernel(float* out, int E) {
    out[0] = (float)(-g_loss_sum / (double)E);
}

// ---------------- Stage A: node GEMM uv = feat @ [W1_top | W1_bot] ----------------
__device__ __forceinline__ void pre_gather(uint32_t Abuf, int t, int tid) {
    const int r = tid >> 2, part = tid & 3;
    int node = t * TILE_M + r;
    if (node > 99999) node = 99999;
    const char* src = reinterpret_cast<const char*>(g_feat_bf16) + (size_t)node * 256;
    #pragma unroll
    for (int q = 0; q < 4; ++q) {
        const int c  = part * 4 + q;
        const int cs = (c & 8) | ((c & 7) ^ (r & 7));
        asm volatile("cp.async.cg.shared.global [%0], [%1], 16;"
                     :: "r"(Abuf + (uint32_t)r * 256u + (uint32_t)cs * 16u),
                        "l"(src + c * 16) : "memory");
    }
}

__global__ __launch_bounds__(PRE_THREADS, 1)
void hx_pre_gemm(const float* __restrict__ b1, int ntiles)
{
    extern __shared__ char dyn[];
    const int tid  = threadIdx.x;
    const int lane = tid & 31;
    const int warp = tid >> 5;

    const uint32_t dynb = smem_u32(dyn);
    const uint32_t base = (dynb + 255u) & ~255u;
    const uint32_t Bsm  = base;
    const uint32_t Asm0 = base + PRE_B_BYTES;

    const int warp_m = warp & 1, warp_n = warp >> 1;
    const int m_base = warp_m * 64, n_base = warp_n * 32;
    const int quad = lane >> 2, qlane = lane & 3;

    if (blockIdx.x < ntiles) pre_gather(Asm0, blockIdx.x, tid);
    asm volatile("cp.async.commit_group;" ::: "memory");
    {
        char* dst = dyn + (base - dynb);
        const int4* s = reinterpret_cast<const int4*>(g_w1pre);
        int4* d = reinterpret_cast<int4*>(dst);
        for (int i = tid; i < PRE_B_BYTES / 16; i += PRE_THREADS) d[i] = s[i];
    }

    float2 bb[4];
    #pragma unroll
    for (int j = 0; j < 4; ++j) {
        const int n = n_base + j * 8 + qlane * 2;
        bb[j] = (n < 128) ? make_float2(b1[n], b1[n + 1]) : make_float2(0.f, 0.f);
    }

    uint32_t rowA[4];
    #pragma unroll
    for (int i = 0; i < 4; ++i)
        rowA[i] = (uint32_t)(m_base + i * 16 + (lane & 15)) * 256u;
    const int xA  = lane & 7;
    const int csA = lane >> 4;

    uint32_t bBase[2];
    {
        const int kr = lane & 15;
        #pragma unroll
        for (int j2 = 0; j2 < 2; ++j2) {
            const int cn = warp_n * 4 + j2 * 2 + (lane >> 4);
            const int cs = (cn & 24) | ((cn & 7) ^ (kr & 7));
            bBase[j2] = Bsm + (uint32_t)kr * 512u + (uint32_t)cs * 16u;
        }
    }

    int li = 0;
    for (int t = blockIdx.x; t < ntiles; t += gridDim.x, ++li) {
        const int buf = li & 1;
        const uint32_t Abuf = Asm0 + (uint32_t)buf * PRE_A_BYTES;

        asm volatile("cp.async.wait_group 0;" ::: "memory");
        __syncthreads();

        const int tn = t + gridDim.x;
        if (tn < ntiles) {
            pre_gather(Asm0 + (uint32_t)(buf ^ 1) * PRE_A_BYTES, tn, tid);
            asm volatile("cp.async.commit_group;" ::: "memory");
        }

        float acc[4][4][4];
        #pragma unroll
        for (int i = 0; i < 4; ++i)
            #pragma unroll
            for (int j = 0; j < 4; ++j) {
                acc[i][j][0] = 0.f; acc[i][j][1] = 0.f;
                acc[i][j][2] = 0.f; acc[i][j][3] = 0.f;
            }

        #pragma unroll
        for (int ks = 0; ks < 8; ++ks) {
            uint32_t b[2][4], a[4][4];
            #pragma unroll
            for (int j2 = 0; j2 < 2; ++j2)
                LDSM_X4T(b[j2], bBase[j2] + (uint32_t)ks * 8192u);
            const int c  = 2 * ks + csA;
            const int cs = (c & 8) | ((c & 7) ^ xA);
            #pragma unroll
            for (int i = 0; i < 4; ++i)
                LDSM_X4(a[i], Abuf + rowA[i] + (uint32_t)cs * 16u);
            #pragma unroll
            for (int i = 0; i < 4; ++i)
                #pragma unroll
                for (int j = 0; j < 4; ++j) {
                    const uint32_t bb0 = b[j >> 1][(j & 1) * 2];
                    const uint32_t bb1 = b[j >> 1][(j & 1) * 2 + 1];
                    asm volatile(
                        "mma.sync.aligned.m16n8k16.row.col.f32.bf16.bf16.f32 "
                        "{%0,%1,%2,%3}, {%4,%5,%6,%7}, {%8,%9}, {%0,%1,%2,%3};"
                        : "+f"(acc[i][j][0]), "+f"(acc[i][j][1]),
                          "+f"(acc[i][j][2]), "+f"(acc[i][j][3])
                        : "r"(a[i][0]), "r"(a[i][1]), "r"(a[i][2]), "r"(a[i][3]),
                          "r"(bb0), "r"(bb1));
                }
        }

        #pragma unroll
        for (int i = 0; i < 4; ++i) {
            const int m0 = m_base + i * 16 + quad;
            const size_t r0 = (size_t)(t * TILE_M + m0) * PRE_N;
            const size_t r1 = (size_t)(t * TILE_M + m0 + 8) * PRE_N;
            #pragma unroll
            for (int j = 0; j < 4; ++j) {
                const int n = n_base + j * 8 + qlane * 2;
                __nv_bfloat162 p = __floats2bfloat162_rn(acc[i][j][0] + bb[j].x,
                                                         acc[i][j][1] + bb[j].y);
                __nv_bfloat162 q = __floats2bfloat162_rn(acc[i][j][2] + bb[j].x,
                                                         acc[i][j][3] + bb[j].y);
                *reinterpret_cast<__nv_bfloat162*>(&g_uv[r0 + n]) = p;
                *reinterpret_cast<__nv_bfloat162*>(&g_uv[r1 + n]) = q;
            }
        }
        __syncthreads();
    }
}

// ---------------- Stage B: per-edge loss, 4 edges/warp, 8 lanes/edge ----------------
__global__ __launch_bounds__(EDGE_THREADS, 2)
void hx_edge(const float* __restrict__ alpha,
             const float* __restrict__ W2,
             const float* __restrict__ b2,
             const int* __restrict__ row,
             const int* __restrict__ col,
             const int* __restrict__ label,
             int E)
{
    __shared__ double s_dsum;
    const int tid  = threadIdx.x;
    const int lane = tid & 31;
    const int warp = tid >> 5;
    if (tid == 0) s_dsum = 0.0;
    __syncthreads();

    const int sub = lane >> 3;         // edge within group (0..3)
    const int sl  = lane & 7;          // lane within edge (0..7)
    const int ch0 = sl * 16;           // 16 channels per lane

    // per-lane constants for 16 channels
    float al[16], wa[16], wb[16];
    #pragma unroll
    for (int i = 0; i < 16; ++i) {
        al[i] = __ldg(&alpha[ch0 + i]);
        wa[i] = __ldg(&W2[(ch0 + i) * 2]);
        wb[i] = __ldg(&W2[(ch0 + i) * 2 + 1]);
    }
    const float bias0 = b2[0], bias1 = b2[1];

    const int gw = blockIdx.x * (EDGE_THREADS / 32) + warp;
    const int nw = gridDim.x * (EDGE_THREADS / 32);
    const int NG = (E + 3) >> 2;       // groups of 4 edges

    double dsum = 0.0;

    if (gw < NG) {
        // ---- pipeline prologue: indices + labels for first group ----
        int e0 = gw * 4 + sub; if (e0 >= E) e0 = E - 1;
        int rc = __ldg(&row[e0]), cc = __ldg(&col[e0]);
        int la = __ldg(&label[rc]), lb = __ldg(&label[cc]);

        for (int g = gw; g < NG; g += nw) {
            // ---- issue uv loads for current group (4x uint4, coalesced) ----
            const __nv_bfloat16* uP = &g_uv[(size_t)rc * PRE_N + ch0];
            const __nv_bfloat16* vP = &g_uv[(size_t)cc * PRE_N + 128 + ch0];
            const uint4 ua  = *reinterpret_cast<const uint4*>(uP);
            const uint4 ub2 = *reinterpret_cast<const uint4*>(uP + 8);
            const uint4 va  = *reinterpret_cast<const uint4*>(vP);
            const uint4 vb2 = *reinterpret_cast<const uint4*>(vP + 8);

            // ---- prefetch next group's indices + labels ----
            int rn = 0, cn = 0, lan = 0, lbn = 0;
            const int g2 = g + nw;
            if (g2 < NG) {
                int e2 = g2 * 4 + sub; if (e2 >= E) e2 = E - 1;
                rn = __ldg(&row[e2]);  cn = __ldg(&col[e2]);
                lan = __ldg(&label[rn]); lbn = __ldg(&label[cn]);
            }

            // ---- compute: PReLU + 128->2 projection over 16 channels ----
            float p0 = 0.f, p1 = 0.f;
            const uint32_t uw[8] = {ua.x, ua.y, ua.z, ua.w, ub2.x, ub2.y, ub2.z, ub2.w};
            const uint32_t vw[8] = {va.x, va.y, va.z, va.w, vb2.x, vb2.y, vb2.z, vb2.w};
            #pragma unroll
            for (int i = 0; i < 8; ++i) {
                const float2 uu = __bfloat1622float2(
                    *reinterpret_cast<const __nv_bfloat162*>(&uw[i]));
                const float2 vv = __bfloat1622float2(
                    *reinterpret_cast<const __nv_bfloat162*>(&vw[i]));
                float h, ph;
                h  = uu.x + vv.x;
                ph = fmaf(al[i * 2], fminf(h, 0.f), fmaxf(h, 0.f));
                p0 = fmaf(ph, wa[i * 2], p0);  p1 = fmaf(ph, wb[i * 2], p1);
                h  = uu.y + vv.y;
                ph = fmaf(al[i * 2 + 1], fminf(h, 0.f), fmaxf(h, 0.f));
                p0 = fmaf(ph, wa[i * 2 + 1], p0);  p1 = fmaf(ph, wb[i * 2 + 1], p1);
            }
            // ---- 8-lane butterfly (stays within each edge's lane group) ----
            #pragma unroll
            for (int off = 4; off > 0; off >>= 1) {
                p0 += __shfl_xor_sync(0xffffffffu, p0, off);
                p1 += __shfl_xor_sync(0xffffffffu, p1, off);
            }
            if (sl == 0) {
                const int ecur = g * 4 + sub;
                if (ecur < E) {
                    const float l0 = p0 + bias0;
                    const float l1 = p1 + bias1;
                    const float mx  = fmaxf(l0, l1);
                    const float lse = mx + log1pf(expf(-fabsf(l0 - l1)));
                    dsum += (double)(((la == lb) ? l1 : l0) - lse);
                }
            }
            rc = rn; cc = cn; la = lan; lb = lbn;
        }
    }

    if (sl == 0) atomicAdd(&s_dsum, dsum);
    __syncthreads();
    if (tid == 0) atomicAdd(&g_loss_sum, s_dsum);
}

extern "C" void kernel_launch(void* const* d_in, const int* in_sizes, int n_in,
                              void* d_out, int out_size) {
    const float* feature = (const float*)d_in[0];
    const float* W1      = (const float*)d_in[1];
    const float* b1      = (const float*)d_in[2];
    const float* alpha   = (const float*)d_in[3];
    const float* W2      = (const float*)d_in[4];
    const float* b2      = (const float*)d_in[5];
    const int*   row     = (const int*)d_in[6];
    const int*   col     = (const int*)d_in[7];
    const int*   label   = (const int*)d_in[8];
    const int E  = in_sizes[6];
    const int nf = in_sizes[0];
    float* out = (float*)d_out;

    int sms = 148;
    cudaDeviceGetAttribute(&sms, cudaDevAttrMultiProcessorCount, 0);
    cudaFuncSetAttribute(hx_pre_gemm,
                         cudaFuncAttributeMaxDynamicSharedMemorySize, PRE_DSMEM);

    hx_init_kernel<<<1, 1>>>();
    hx_prep_feat<<<(nf / 4 + 255) / 256, 256>>>(feature, nf / 4);
    hx_prep_w1pre<<<(PRE_K * PRE_N) / 256, 256>>>(W1);

    const int nnodes = in_sizes[0] / NHID;
    const int ntiles = (nnodes + TILE_M - 1) / TILE_M;
    hx_pre_gemm<<<sms, PRE_THREADS, PRE_DSMEM>>>(b1, ntiles);

    hx_edge<<<sms * 2, EDGE_THREADS>>>(alpha, W2, b2, row, col, label, E);
    hx_final_kernel<<<1, 1>>>(out, E);
}

// round 13
// speedup vs baseline: 1.9322x; 1.1975x over previous
#include <cuda_runtime.h>
#include <cuda_bf16.h>
#include <cstdint>

// R13: R12 + fully software-pipelined edge kernel: uv(next), label(next) and
// idx(next2) all issued during compute(cur) -> no load is consumed in the
// iteration it was issued; per-iteration exposed L2 latency ~0.

namespace {
constexpr int NHID     = 128;
constexpr int PRE_N    = 256;                 // u(128) | v(128)
constexpr int PRE_K    = 128;
constexpr int TILE_M   = 128;
constexpr int PRE_THREADS = 512;
constexpr int N_NODES_PAD = 100096;           // 782 * 128
constexpr int PRE_B_BYTES = PRE_K * PRE_N * 2;    // 64 KB
constexpr int PRE_A_BYTES = TILE_M * PRE_K * 2;   // 32 KB
constexpr int PRE_DSMEM   = PRE_B_BYTES + 2 * PRE_A_BYTES + 256;
constexpr int EDGE_THREADS = 256;
}

__device__ __align__(16) __nv_bfloat16 g_feat_bf16[(size_t)100000 * NHID];
__device__ __align__(16) __nv_bfloat16 g_w1pre[PRE_K * PRE_N];   // swizzled B image
__device__ __align__(16) __nv_bfloat16 g_uv[(size_t)N_NODES_PAD * PRE_N];
__device__ double g_loss_sum;

__device__ __forceinline__ uint32_t smem_u32(const void* p) {
    uint32_t a;
    asm("{ .reg .u64 t; cvta.to.shared.u64 t, %1; cvt.u32.u64 %0, t; }" : "=r"(a) : "l"(p));
    return a;
}

#define LDSM_X4(r, addr) \
    asm volatile("ldmatrix.sync.aligned.m8n8.x4.shared.b16 {%0,%1,%2,%3}, [%4];" \
        : "=r"((r)[0]), "=r"((r)[1]), "=r"((r)[2]), "=r"((r)[3]) : "r"(addr))
#define LDSM_X4T(r, addr) \
    asm volatile("ldmatrix.sync.aligned.m8n8.x4.trans.shared.b16 {%0,%1,%2,%3}, [%4];" \
        : "=r"((r)[0]), "=r"((r)[1]), "=r"((r)[2]), "=r"((r)[3]) : "r"(addr))

// ---------------- prep kernels ----------------
__global__ void hx_init_kernel() { g_loss_sum = 0.0; }

__global__ void hx_prep_feat(const float* __restrict__ f, int n4) {
    int i = blockIdx.x * blockDim.x + threadIdx.x;
    if (i < n4) {
        float4 v = reinterpret_cast<const float4*>(f)[i];
        __nv_bfloat162* dst = reinterpret_cast<__nv_bfloat162*>(g_feat_bf16);
        dst[i * 2]     = __floats2bfloat162_rn(v.x, v.y);
        dst[i * 2 + 1] = __floats2bfloat162_rn(v.z, v.w);
    }
}

__global__ void hx_prep_w1pre(const float* __restrict__ W1) {
    int idx = blockIdx.x * blockDim.x + threadIdx.x;   // 32768
    int k = idx >> 8, np = idx & 255;
    int srow = k + ((np >> 7) << 7);
    int scol = np & 127;
    int c  = np >> 3;
    int cs = (c & 24) | ((c & 7) ^ (k & 7));
    uint32_t off = (uint32_t)k * 512u + (uint32_t)cs * 16u + (uint32_t)(np & 7) * 2u;
    *reinterpret_cast<__nv_bfloat16*>(reinterpret_cast<char*>(g_w1pre) + off) =
        __float2bfloat16(W1[srow * 128 + scol]);
}

__global__ void hx_final_kernel(float* out, int E) {
    out[0] = (float)(-g_loss_sum / (double)E);
}

// ---------------- Stage A: node GEMM uv = feat @ [W1_top | W1_bot] ----------------
__device__ __forceinline__ void pre_gather(uint32_t Abuf, int t, int tid) {
    const int r = tid >> 2, part = tid & 3;
    int node = t * TILE_M + r;
    if (node > 99999) node = 99999;
    const char* src = reinterpret_cast<const char*>(g_feat_bf16) + (size_t)node * 256;
    #pragma unroll
    for (int q = 0; q < 4; ++q) {
        const int c  = part * 4 + q;
        const int cs = (c & 8) | ((c & 7) ^ (r & 7));
        asm volatile("cp.async.cg.shared.global [%0], [%1], 16;"
                     :: "r"(Abuf + (uint32_t)r * 256u + (uint32_t)cs * 16u),
                        "l"(src + c * 16) : "memory");
    }
}

__global__ __launch_bounds__(PRE_THREADS, 1)
void hx_pre_gemm(const float* __restrict__ b1, int ntiles)
{
    extern __shared__ char dyn[];
    const int tid  = threadIdx.x;
    const int lane = tid & 31;
    const int warp = tid >> 5;

    const uint32_t dynb = smem_u32(dyn);
    const uint32_t base = (dynb + 255u) & ~255u;
    const uint32_t Bsm  = base;
    const uint32_t Asm0 = base + PRE_B_BYTES;

    const int warp_m = warp & 1, warp_n = warp >> 1;
    const int m_base = warp_m * 64, n_base = warp_n * 32;
    const int quad = lane >> 2, qlane = lane & 3;

    if (blockIdx.x < ntiles) pre_gather(Asm0, blockIdx.x, tid);
    asm volatile("cp.async.commit_group;" ::: "memory");
    {
        char* dst = dyn + (base - dynb);
        const int4* s = reinterpret_cast<const int4*>(g_w1pre);
        int4* d = reinterpret_cast<int4*>(dst);
        for (int i = tid; i < PRE_B_BYTES / 16; i += PRE_THREADS) d[i] = s[i];
    }

    float2 bb[4];
    #pragma unroll
    for (int j = 0; j < 4; ++j) {
        const int n = n_base + j * 8 + qlane * 2;
        bb[j] = (n < 128) ? make_float2(b1[n], b1[n + 1]) : make_float2(0.f, 0.f);
    }

    uint32_t rowA[4];
    #pragma unroll
    for (int i = 0; i < 4; ++i)
        rowA[i] = (uint32_t)(m_base + i * 16 + (lane & 15)) * 256u;
    const int xA  = lane & 7;
    const int csA = lane >> 4;

    uint32_t bBase[2];
    {
        const int kr = lane & 15;
        #pragma unroll
        for (int j2 = 0; j2 < 2; ++j2) {
            const int cn = warp_n * 4 + j2 * 2 + (lane >> 4);
            const int cs = (cn & 24) | ((cn & 7) ^ (kr & 7));
            bBase[j2] = Bsm + (uint32_t)kr * 512u + (uint32_t)cs * 16u;
        }
    }

    int li = 0;
    for (int t = blockIdx.x; t < ntiles; t += gridDim.x, ++li) {
        const int buf = li & 1;
        const uint32_t Abuf = Asm0 + (uint32_t)buf * PRE_A_BYTES;

        asm volatile("cp.async.wait_group 0;" ::: "memory");
        __syncthreads();

        const int tn = t + gridDim.x;
        if (tn < ntiles) {
            pre_gather(Asm0 + (uint32_t)(buf ^ 1) * PRE_A_BYTES, tn, tid);
            asm volatile("cp.async.commit_group;" ::: "memory");
        }

        float acc[4][4][4];
        #pragma unroll
        for (int i = 0; i < 4; ++i)
            #pragma unroll
            for (int j = 0; j < 4; ++j) {
                acc[i][j][0] = 0.f; acc[i][j][1] = 0.f;
                acc[i][j][2] = 0.f; acc[i][j][3] = 0.f;
            }

        #pragma unroll
        for (int ks = 0; ks < 8; ++ks) {
            uint32_t b[2][4], a[4][4];
            #pragma unroll
            for (int j2 = 0; j2 < 2; ++j2)
                LDSM_X4T(b[j2], bBase[j2] + (uint32_t)ks * 8192u);
            const int c  = 2 * ks + csA;
            const int cs = (c & 8) | ((c & 7) ^ xA);
            #pragma unroll
            for (int i = 0; i < 4; ++i)
                LDSM_X4(a[i], Abuf + rowA[i] + (uint32_t)cs * 16u);
            #pragma unroll
            for (int i = 0; i < 4; ++i)
                #pragma unroll
                for (int j = 0; j < 4; ++j) {
                    const uint32_t bb0 = b[j >> 1][(j & 1) * 2];
                    const uint32_t bb1 = b[j >> 1][(j & 1) * 2 + 1];
                    asm volatile(
                        "mma.sync.aligned.m16n8k16.row.col.f32.bf16.bf16.f32 "
                        "{%0,%1,%2,%3}, {%4,%5,%6,%7}, {%8,%9}, {%0,%1,%2,%3};"
                        : "+f"(acc[i][j][0]), "+f"(acc[i][j][1]),
                          "+f"(acc[i][j][2]), "+f"(acc[i][j][3])
                        : "r"(a[i][0]), "r"(a[i][1]), "r"(a[i][2]), "r"(a[i][3]),
                          "r"(bb0), "r"(bb1));
                }
        }

        #pragma unroll
        for (int i = 0; i < 4; ++i) {
            const int m0 = m_base + i * 16 + quad;
            const size_t r0 = (size_t)(t * TILE_M + m0) * PRE_N;
            const size_t r1 = (size_t)(t * TILE_M + m0 + 8) * PRE_N;
            #pragma unroll
            for (int j = 0; j < 4; ++j) {
                const int n = n_base + j * 8 + qlane * 2;
                __nv_bfloat162 p = __floats2bfloat162_rn(acc[i][j][0] + bb[j].x,
                                                         acc[i][j][1] + bb[j].y);
                __nv_bfloat162 q = __floats2bfloat162_rn(acc[i][j][2] + bb[j].x,
                                                         acc[i][j][3] + bb[j].y);
                *reinterpret_cast<__nv_bfloat162*>(&g_uv[r0 + n]) = p;
                *reinterpret_cast<__nv_bfloat162*>(&g_uv[r1 + n]) = q;
            }
        }
        __syncthreads();
    }
}

// ---------------- Stage B: per-edge loss, depth-2 register pipeline ----------------
__global__ __launch_bounds__(EDGE_THREADS, 2)
void hx_edge(const float* __restrict__ alpha,
             const float* __restrict__ W2,
             const float* __restrict__ b2,
             const int* __restrict__ row,
             const int* __restrict__ col,
             const int* __restrict__ label,
             int E)
{
    __shared__ double s_dsum;
    const int tid  = threadIdx.x;
    const int lane = tid & 31;
    const int warp = tid >> 5;
    if (tid == 0) s_dsum = 0.0;
    __syncthreads();

    const int sub = lane >> 3;         // edge within group (0..3)
    const int sl  = lane & 7;          // lane within edge (0..7)
    const int ch0 = sl * 16;           // 16 channels per lane

    float al[16], wa[16], wb[16];
    #pragma unroll
    for (int i = 0; i < 16; ++i) {
        al[i] = __ldg(&alpha[ch0 + i]);
        wa[i] = __ldg(&W2[(ch0 + i) * 2]);
        wb[i] = __ldg(&W2[(ch0 + i) * 2 + 1]);
    }
    const float bias0 = b2[0], bias1 = b2[1];

    const int gw = blockIdx.x * (EDGE_THREADS / 32) + warp;
    const int nw = gridDim.x * (EDGE_THREADS / 32);
    const int NG = (E + 3) >> 2;       // groups of 4 edges

    double dsum = 0.0;

    if (gw < NG) {
        // ---- prologue: fill the pipeline ----
        int e0 = gw * 4 + sub; if (e0 >= E) e0 = E - 1;
        int la = 0, lb = 0;
        uint4 Ua, Ub, Va, Vb;
        {
            const int rc = __ldg(&row[e0]), cc = __ldg(&col[e0]);
            la = __ldg(&label[rc]); lb = __ldg(&label[cc]);
            const __nv_bfloat16* uP = &g_uv[(size_t)rc * PRE_N + ch0];
            const __nv_bfloat16* vP = &g_uv[(size_t)cc * PRE_N + 128 + ch0];
            Ua = *reinterpret_cast<const uint4*>(uP);
            Ub = *reinterpret_cast<const uint4*>(uP + 8);
            Va = *reinterpret_cast<const uint4*>(vP);
            Vb = *reinterpret_cast<const uint4*>(vP + 8);
        }
        int rn = 0, cn = 0;
        if (gw + nw < NG) {
            int e1 = (gw + nw) * 4 + sub; if (e1 >= E) e1 = E - 1;
            rn = __ldg(&row[e1]); cn = __ldg(&col[e1]);
        }

        for (int g = gw; g < NG; g += nw) {
            const int g1 = g + nw;

            // ---- issue loads for g+nw: uv + labels (idx already resident) ----
            uint4 nUa, nUb, nVa, nVb;
            int lan = 0, lbn = 0;
            if (g1 < NG) {
                const __nv_bfloat16* uP = &g_uv[(size_t)rn * PRE_N + ch0];
                const __nv_bfloat16* vP = &g_uv[(size_t)cn * PRE_N + 128 + ch0];
                nUa = *reinterpret_cast<const uint4*>(uP);
                nUb = *reinterpret_cast<const uint4*>(uP + 8);
                nVa = *reinterpret_cast<const uint4*>(vP);
                nVb = *reinterpret_cast<const uint4*>(vP + 8);
                lan = __ldg(&label[rn]);
                lbn = __ldg(&label[cn]);
            } else {
                nUa = make_uint4(0,0,0,0); nUb = nUa; nVa = nUa; nVb = nUa;
            }
            // ---- issue idx for g+2*nw ----
            int rn2 = 0, cn2 = 0;
            if (g + 2 * nw < NG) {
                int e2 = (g + 2 * nw) * 4 + sub; if (e2 >= E) e2 = E - 1;
                rn2 = __ldg(&row[e2]); cn2 = __ldg(&col[e2]);
            }

            // ---- compute current group (all operands register-resident) ----
            float p0 = 0.f, p1 = 0.f;
            const uint32_t uw[8] = {Ua.x, Ua.y, Ua.z, Ua.w, Ub.x, Ub.y, Ub.z, Ub.w};
            const uint32_t vw[8] = {Va.x, Va.y, Va.z, Va.w, Vb.x, Vb.y, Vb.z, Vb.w};
            #pragma unroll
            for (int i = 0; i < 8; ++i) {
                const float2 uu = __bfloat1622float2(
                    *reinterpret_cast<const __nv_bfloat162*>(&uw[i]));
                const float2 vv = __bfloat1622float2(
                    *reinterpret_cast<const __nv_bfloat162*>(&vw[i]));
                float h, ph;
                h  = uu.x + vv.x;
                ph = fmaf(al[i * 2], fminf(h, 0.f), fmaxf(h, 0.f));
                p0 = fmaf(ph, wa[i * 2], p0);  p1 = fmaf(ph, wb[i * 2], p1);
                h  = uu.y + vv.y;
                ph = fmaf(al[i * 2 + 1], fminf(h, 0.f), fmaxf(h, 0.f));
                p0 = fmaf(ph, wa[i * 2 + 1], p0);  p1 = fmaf(ph, wb[i * 2 + 1], p1);
            }
            #pragma unroll
            for (int off = 4; off > 0; off >>= 1) {
                p0 += __shfl_xor_sync(0xffffffffu, p0, off);
                p1 += __shfl_xor_sync(0xffffffffu, p1, off);
            }
            if (sl == 0) {
                const int ecur = g * 4 + sub;
                if (ecur < E) {
                    const float l0 = p0 + bias0;
                    const float l1 = p1 + bias1;
                    const float mx  = fmaxf(l0, l1);
                    const float lse = mx + log1pf(expf(-fabsf(l0 - l1)));
                    dsum += (double)(((la == lb) ? l1 : l0) - lse);
                }
            }

            // ---- rotate pipeline ----
            Ua = nUa; Ub = nUb; Va = nVa; Vb = nVb;
            la = lan; lb = lbn;
            rn = rn2; cn = cn2;
        }
    }

    if (sl == 0) atomicAdd(&s_dsum, dsum);
    __syncthreads();
    if (tid == 0) atomicAdd(&g_loss_sum, s_dsum);
}

extern "C" void kernel_launch(void* const* d_in, const int* in_sizes, int n_in,
                              void* d_out, int out_size) {
    const float* feature = (const float*)d_in[0];
    const float* W1      = (const float*)d_in[1];
    const float* b1      = (const float*)d_in[2];
    const float* alpha   = (const float*)d_in[3];
    const float* W2      = (const float*)d_in[4];
    const float* b2      = (const float*)d_in[5];
    const int*   row     = (const int*)d_in[6];
    const int*   col     = (const int*)d_in[7];
    const int*   label   = (const int*)d_in[8];
    const int E  = in_sizes[6];
    const int nf = in_sizes[0];
    float* out = (float*)d_out;

    int sms = 148;
    cudaDeviceGetAttribute(&sms, cudaDevAttrMultiProcessorCount, 0);
    cudaFuncSetAttribute(hx_pre_gemm,
                         cudaFuncAttributeMaxDynamicSharedMemorySize, PRE_DSMEM);

    hx_init_kernel<<<1, 1>>>();
    hx_prep_feat<<<(nf / 4 + 255) / 256, 256>>>(feature, nf / 4);
    hx_prep_w1pre<<<(PRE_K * PRE_N) / 256, 256>>>(W1);

    const int nnodes = in_sizes[0] / NHID;
    const int ntiles = (nnodes + TILE_M - 1) / TILE_M;
    hx_pre_gemm<<<sms, PRE_THREADS, PRE_DSMEM>>>(b1, ntiles);

    hx_edge<<<sms * 2, EDGE_THREADS>>>(alpha, W2, b2, row, col, label, E);
    hx_final_kernel<<<1, 1>>>(out, E);
}

// round 14
// speedup vs baseline: 2.1555x; 1.1155x over previous
#include <cuda_runtime.h>
#include <cuda_bf16.h>
#include <cstdint>

// R14: R13 + (a) bf16x2-packed PReLU in the edge kernel (9 instr/2ch vs ~22,
// fp32 accumulation preserved), (b) merged init+feat+W1 prep kernel.

namespace {
constexpr int NHID     = 128;
constexpr int PRE_N    = 256;                 // u(128) | v(128)
constexpr int PRE_K    = 128;
constexpr int TILE_M   = 128;
constexpr int PRE_THREADS = 512;
constexpr int N_NODES_PAD = 100096;           // 782 * 128
constexpr int PRE_B_BYTES = PRE_K * PRE_N * 2;    // 64 KB
constexpr int PRE_A_BYTES = TILE_M * PRE_K * 2;   // 32 KB
constexpr int PRE_DSMEM   = PRE_B_BYTES + 2 * PRE_A_BYTES + 256;
constexpr int EDGE_THREADS = 256;
constexpr int W1_ELEMS = PRE_K * PRE_N;           // 32768
}

__device__ __align__(16) __nv_bfloat16 g_feat_bf16[(size_t)100000 * NHID];
__device__ __align__(16) __nv_bfloat16 g_w1pre[W1_ELEMS];   // swizzled B image
__device__ __align__(16) __nv_bfloat16 g_uv[(size_t)N_NODES_PAD * PRE_N];
__device__ double g_loss_sum;

__device__ __forceinline__ uint32_t smem_u32(const void* p) {
    uint32_t a;
    asm("{ .reg .u64 t; cvta.to.shared.u64 t, %1; cvt.u32.u64 %0, t; }" : "=r"(a) : "l"(p));
    return a;
}

#define LDSM_X4(r, addr) \
    asm volatile("ldmatrix.sync.aligned.m8n8.x4.shared.b16 {%0,%1,%2,%3}, [%4];" \
        : "=r"((r)[0]), "=r"((r)[1]), "=r"((r)[2]), "=r"((r)[3]) : "r"(addr))
#define LDSM_X4T(r, addr) \
    asm volatile("ldmatrix.sync.aligned.m8n8.x4.trans.shared.b16 {%0,%1,%2,%3}, [%4];" \
        : "=r"((r)[0]), "=r"((r)[1]), "=r"((r)[2]), "=r"((r)[3]) : "r"(addr))

// ---------------- merged prep: loss init + feat fp32->bf16 + W1 image ----------------
__global__ void hx_prep(const float* __restrict__ f,
                        const float* __restrict__ W1, int n4)
{
    const int i = blockIdx.x * blockDim.x + threadIdx.x;
    if (i == 0) g_loss_sum = 0.0;
    if (i < n4) {
        float4 v = reinterpret_cast<const float4*>(f)[i];
        __nv_bfloat162* dst = reinterpret_cast<__nv_bfloat162*>(g_feat_bf16);
        dst[i * 2]     = __floats2bfloat162_rn(v.x, v.y);
        dst[i * 2 + 1] = __floats2bfloat162_rn(v.z, v.w);
    } else if (i < n4 + W1_ELEMS) {
        const int idx = i - n4;
        const int k = idx >> 8, np = idx & 255;
        const int srow = k + ((np >> 7) << 7);
        const int scol = np & 127;
        const int c  = np >> 3;
        const int cs = (c & 24) | ((c & 7) ^ (k & 7));
        const uint32_t off = (uint32_t)k * 512u + (uint32_t)cs * 16u + (uint32_t)(np & 7) * 2u;
        *reinterpret_cast<__nv_bfloat16*>(reinterpret_cast<char*>(g_w1pre) + off) =
            __float2bfloat16(W1[srow * 128 + scol]);
    }
}

__global__ void hx_final_kernel(float* out, int E) {
    out[0] = (float)(-g_loss_sum / (double)E);
}

// ---------------- Stage A: node GEMM uv = feat @ [W1_top | W1_bot] ----------------
__device__ __forceinline__ void pre_gather(uint32_t Abuf, int t, int tid) {
    const int r = tid >> 2, part = tid & 3;
    int node = t * TILE_M + r;
    if (node > 99999) node = 99999;
    const char* src = reinterpret_cast<const char*>(g_feat_bf16) + (size_t)node * 256;
    #pragma unroll
    for (int q = 0; q < 4; ++q) {
        const int c  = part * 4 + q;
        const int cs = (c & 8) | ((c & 7) ^ (r & 7));
        asm volatile("cp.async.cg.shared.global [%0], [%1], 16;"
                     :: "r"(Abuf + (uint32_t)r * 256u + (uint32_t)cs * 16u),
                        "l"(src + c * 16) : "memory");
    }
}

__global__ __launch_bounds__(PRE_THREADS, 1)
void hx_pre_gemm(const float* __restrict__ b1, int ntiles)
{
    extern __shared__ char dyn[];
    const int tid  = threadIdx.x;
    const int lane = tid & 31;
    const int warp = tid >> 5;

    const uint32_t dynb = smem_u32(dyn);
    const uint32_t base = (dynb + 255u) & ~255u;
    const uint32_t Bsm  = base;
    const uint32_t Asm0 = base + PRE_B_BYTES;

    const int warp_m = warp & 1, warp_n = warp >> 1;
    const int m_base = warp_m * 64, n_base = warp_n * 32;
    const int quad = lane >> 2, qlane = lane & 3;

    if (blockIdx.x < ntiles) pre_gather(Asm0, blockIdx.x, tid);
    asm volatile("cp.async.commit_group;" ::: "memory");
    {
        char* dst = dyn + (base - dynb);
        const int4* s = reinterpret_cast<const int4*>(g_w1pre);
        int4* d = reinterpret_cast<int4*>(dst);
        for (int i = tid; i < PRE_B_BYTES / 16; i += PRE_THREADS) d[i] = s[i];
    }

    float2 bb[4];
    #pragma unroll
    for (int j = 0; j < 4; ++j) {
        const int n = n_base + j * 8 + qlane * 2;
        bb[j] = (n < 128) ? make_float2(b1[n], b1[n + 1]) : make_float2(0.f, 0.f);
    }

    uint32_t rowA[4];
    #pragma unroll
    for (int i = 0; i < 4; ++i)
        rowA[i] = (uint32_t)(m_base + i * 16 + (lane & 15)) * 256u;
    const int xA  = lane & 7;
    const int csA = lane >> 4;

    uint32_t bBase[2];
    {
        const int kr = lane & 15;
        #pragma unroll
        for (int j2 = 0; j2 < 2; ++j2) {
            const int cn = warp_n * 4 + j2 * 2 + (lane >> 4);
            const int cs = (cn & 24) | ((cn & 7) ^ (kr & 7));
            bBase[j2] = Bsm + (uint32_t)kr * 512u + (uint32_t)cs * 16u;
        }
    }

    int li = 0;
    for (int t = blockIdx.x; t < ntiles; t += gridDim.x, ++li) {
        const int buf = li & 1;
        const uint32_t Abuf = Asm0 + (uint32_t)buf * PRE_A_BYTES;

        asm volatile("cp.async.wait_group 0;" ::: "memory");
        __syncthreads();

        const int tn = t + gridDim.x;
        if (tn < ntiles) {
            pre_gather(Asm0 + (uint32_t)(buf ^ 1) * PRE_A_BYTES, tn, tid);
            asm volatile("cp.async.commit_group;" ::: "memory");
        }

        float acc[4][4][4];
        #pragma unroll
        for (int i = 0; i < 4; ++i)
            #pragma unroll
            for (int j = 0; j < 4; ++j) {
                acc[i][j][0] = 0.f; acc[i][j][1] = 0.f;
                acc[i][j][2] = 0.f; acc[i][j][3] = 0.f;
            }

        #pragma unroll
        for (int ks = 0; ks < 8; ++ks) {
            uint32_t b[2][4], a[4][4];
            #pragma unroll
            for (int j2 = 0; j2 < 2; ++j2)
                LDSM_X4T(b[j2], bBase[j2] + (uint32_t)ks * 8192u);
            const int c  = 2 * ks + csA;
            const int cs = (c & 8) | ((c & 7) ^ xA);
            #pragma unroll
            for (int i = 0; i < 4; ++i)
                LDSM_X4(a[i], Abuf + rowA[i] + (uint32_t)cs * 16u);
            #pragma unroll
            for (int i = 0; i < 4; ++i)
                #pragma unroll
                for (int j = 0; j < 4; ++j) {
                    const uint32_t bb0 = b[j >> 1][(j & 1) * 2];
                    const uint32_t bb1 = b[j >> 1][(j & 1) * 2 + 1];
                    asm volatile(
                        "mma.sync.aligned.m16n8k16.row.col.f32.bf16.bf16.f32 "
                        "{%0,%1,%2,%3}, {%4,%5,%6,%7}, {%8,%9}, {%0,%1,%2,%3};"
                        : "+f"(acc[i][j][0]), "+f"(acc[i][j][1]),
                          "+f"(acc[i][j][2]), "+f"(acc[i][j][3])
                        : "r"(a[i][0]), "r"(a[i][1]), "r"(a[i][2]), "r"(a[i][3]),
                          "r"(bb0), "r"(bb1));
                }
        }

        #pragma unroll
        for (int i = 0; i < 4; ++i) {
            const int m0 = m_base + i * 16 + quad;
            const size_t r0 = (size_t)(t * TILE_M + m0) * PRE_N;
            const size_t r1 = (size_t)(t * TILE_M + m0 + 8) * PRE_N;
            #pragma unroll
            for (int j = 0; j < 4; ++j) {
                const int n = n_base + j * 8 + qlane * 2;
                __nv_bfloat162 p = __floats2bfloat162_rn(acc[i][j][0] + bb[j].x,
                                                         acc[i][j][1] + bb[j].y);
                __nv_bfloat162 q = __floats2bfloat162_rn(acc[i][j][2] + bb[j].x,
                                                         acc[i][j][3] + bb[j].y);
                *reinterpret_cast<__nv_bfloat162*>(&g_uv[r0 + n]) = p;
                *reinterpret_cast<__nv_bfloat162*>(&g_uv[r1 + n]) = q;
            }
        }
        __syncthreads();
    }
}

// ---------------- Stage B: per-edge loss, packed-bf16 PReLU, depth-2 pipeline ----------------
__global__ __launch_bounds__(EDGE_THREADS, 2)
void hx_edge(const float* __restrict__ alpha,
             const float* __restrict__ W2,
             const float* __restrict__ b2,
             const int* __restrict__ row,
             const int* __restrict__ col,
             const int* __restrict__ label,
             int E)
{
    __shared__ double s_dsum;
    const int tid  = threadIdx.x;
    const int lane = tid & 31;
    const int warp = tid >> 5;
    if (tid == 0) s_dsum = 0.0;
    __syncthreads();

    const int sub = lane >> 3;         // edge within group (0..3)
    const int sl  = lane & 7;          // lane within edge (0..7)
    const int ch0 = sl * 16;           // 16 channels per lane

    __nv_bfloat162 al2[8];
    float wa[16], wb[16];
    #pragma unroll
    for (int i = 0; i < 8; ++i)
        al2[i] = __floats2bfloat162_rn(__ldg(&alpha[ch0 + 2 * i]),
                                       __ldg(&alpha[ch0 + 2 * i + 1]));
    #pragma unroll
    for (int i = 0; i < 16; ++i) {
        wa[i] = __ldg(&W2[(ch0 + i) * 2]);
        wb[i] = __ldg(&W2[(ch0 + i) * 2 + 1]);
    }
    const float bias0 = b2[0], bias1 = b2[1];
    const __nv_bfloat162 z2 = __floats2bfloat162_rn(0.f, 0.f);

    const int gw = blockIdx.x * (EDGE_THREADS / 32) + warp;
    const int nw = gridDim.x * (EDGE_THREADS / 32);
    const int NG = (E + 3) >> 2;       // groups of 4 edges

    double dsum = 0.0;

    if (gw < NG) {
        // ---- prologue: fill the pipeline ----
        int e0 = gw * 4 + sub; if (e0 >= E) e0 = E - 1;
        int la = 0, lb = 0;
        uint4 Ua, Ub, Va, Vb;
        {
            const int rc = __ldg(&row[e0]), cc = __ldg(&col[e0]);
            la = __ldg(&label[rc]); lb = __ldg(&label[cc]);
            const __nv_bfloat16* uP = &g_uv[(size_t)rc * PRE_N + ch0];
            const __nv_bfloat16* vP = &g_uv[(size_t)cc * PRE_N + 128 + ch0];
            Ua = *reinterpret_cast<const uint4*>(uP);
            Ub = *reinterpret_cast<const uint4*>(uP + 8);
            Va = *reinterpret_cast<const uint4*>(vP);
            Vb = *reinterpret_cast<const uint4*>(vP + 8);
        }
        int rn = 0, cn = 0;
        if (gw + nw < NG) {
            int e1 = (gw + nw) * 4 + sub; if (e1 >= E) e1 = E - 1;
            rn = __ldg(&row[e1]); cn = __ldg(&col[e1]);
        }

        for (int g = gw; g < NG; g += nw) {
            const int g1 = g + nw;

            // ---- issue loads for g+nw: uv + labels ----
            uint4 nUa, nUb, nVa, nVb;
            int lan = 0, lbn = 0;
            if (g1 < NG) {
                const __nv_bfloat16* uP = &g_uv[(size_t)rn * PRE_N + ch0];
                const __nv_bfloat16* vP = &g_uv[(size_t)cn * PRE_N + 128 + ch0];
                nUa = *reinterpret_cast<const uint4*>(uP);
                nUb = *reinterpret_cast<const uint4*>(uP + 8);
                nVa = *reinterpret_cast<const uint4*>(vP);
                nVb = *reinterpret_cast<const uint4*>(vP + 8);
                lan = __ldg(&label[rn]);
                lbn = __ldg(&label[cn]);
            } else {
                nUa = make_uint4(0,0,0,0); nUb = nUa; nVa = nUa; nVb = nUa;
            }
            // ---- issue idx for g+2*nw ----
            int rn2 = 0, cn2 = 0;
            if (g + 2 * nw < NG) {
                int e2 = (g + 2 * nw) * 4 + sub; if (e2 >= E) e2 = E - 1;
                rn2 = __ldg(&row[e2]); cn2 = __ldg(&col[e2]);
            }

            // ---- compute current group: packed bf16 PReLU + fp32 projection ----
            float p0 = 0.f, p1 = 0.f;
            const uint32_t uw[8] = {Ua.x, Ua.y, Ua.z, Ua.w, Ub.x, Ub.y, Ub.z, Ub.w};
            const uint32_t vw[8] = {Va.x, Va.y, Va.z, Va.w, Vb.x, Vb.y, Vb.z, Vb.w};
            #pragma unroll
            for (int i = 0; i < 8; ++i) {
                const __nv_bfloat162 u2 = *reinterpret_cast<const __nv_bfloat162*>(&uw[i]);
                const __nv_bfloat162 v2 = *reinterpret_cast<const __nv_bfloat162*>(&vw[i]);
                const __nv_bfloat162 h2 = __hadd2(u2, v2);
                const __nv_bfloat162 ph2 =
                    __hfma2(al2[i], __hmin2(h2, z2), __hmax2(h2, z2));
                const float2 f = __bfloat1622float2(ph2);
                p0 = fmaf(f.x, wa[2 * i], p0);      p1 = fmaf(f.x, wb[2 * i], p1);
                p0 = fmaf(f.y, wa[2 * i + 1], p0);  p1 = fmaf(f.y, wb[2 * i + 1], p1);
            }
            #pragma unroll
            for (int off = 4; off > 0; off >>= 1) {
                p0 += __shfl_xor_sync(0xffffffffu, p0, off);
                p1 += __shfl_xor_sync(0xffffffffu, p1, off);
            }
            if (sl == 0) {
                const int ecur = g * 4 + sub;
                if (ecur < E) {
                    const float l0 = p0 + bias0;
                    const float l1 = p1 + bias1;
                    const float mx  = fmaxf(l0, l1);
                    const float lse = mx + log1pf(expf(-fabsf(l0 - l1)));
                    dsum += (double)(((la == lb) ? l1 : l0) - lse);
                }
            }

            // ---- rotate pipeline ----
            Ua = nUa; Ub = nUb; Va = nVa; Vb = nVb;
            la = lan; lb = lbn;
            rn = rn2; cn = cn2;
        }
    }

    if (sl == 0) atomicAdd(&s_dsum, dsum);
    __syncthreads();
    if (tid == 0) atomicAdd(&g_loss_sum, s_dsum);
}

extern "C" void kernel_launch(void* const* d_in, const int* in_sizes, int n_in,
                              void* d_out, int out_size) {
    const float* feature = (const float*)d_in[0];
    const float* W1      = (const float*)d_in[1];
    const float* b1      = (const float*)d_in[2];
    const float* alpha   = (const float*)d_in[3];
    const float* W2      = (const float*)d_in[4];
    const float* b2      = (const float*)d_in[5];
    const int*   row     = (const int*)d_in[6];
    const int*   col     = (const int*)d_in[7];
    const int*   label   = (const int*)d_in[8];
    const int E  = in_sizes[6];
    const int nf = in_sizes[0];
    float* out = (float*)d_out;

    int sms = 148;
    cudaDeviceGetAttribute(&sms, cudaDevAttrMultiProcessorCount, 0);
    cudaFuncSetAttribute(hx_pre_gemm,
                         cudaFuncAttributeMaxDynamicSharedMemorySize, PRE_DSMEM);

    const int n4 = nf / 4;
    hx_prep<<<(n4 + W1_ELEMS + 255) / 256, 256>>>(feature, W1, n4);

    const int nnodes = nf / NHID;
    const int ntiles = (nnodes + TILE_M - 1) / TILE_M;
    hx_pre_gemm<<<sms, PRE_THREADS, PRE_DSMEM>>>(b1, ntiles);

    hx_edge<<<sms * 2, EDGE_THREADS>>>(alpha, W2, b2, row, col, label, E);
    hx_final_kernel<<<1, 1>>>(out, E);
}